// round 16
// baseline (speedup 1.0000x reference)
#include <cuda_runtime.h>
#include <stdint.h>

#define VOCAB 50257
#define SEQ   512
#define BATCH 8
#define KD    4      // NUM_DRAFTS
#define LD    8      // DRAFT_LEN
#define NROWS 256    // KD*LD*BATCH
#define LOGITS_ELEMS (BATCH * SEQ * VOCAB)
#define GX    4      // blocks per row; stride = GX*256 = 1024
#define STRIDE 1024
#define PREPP 4      // prep slices per batch row
#define YDIM  (BATCH / 1 + NROWS)   // not used; kept simple below
#define TOTALB (GX * (NROWS + 8))   // 1056: y 0..7 prep, y 8..263 sampler

// Per-(row,gx) winners + softmax partials, plain store each launch
__device__ unsigned long long g_part[NROWS * GX];
__device__ float g_pmax[BATCH * PREPP];
__device__ float g_psum[BATCH * PREPP];
__device__ unsigned int g_done;          // self-resetting completion counter

// ---- JAX partitionable threefry bits for flat index i (< 2^32):
//      (o0, o1) = threefry2x32(key=(0,42), x0=0, x1=i);  bits = o0 ^ o1
__device__ __forceinline__ uint32_t tf_bits(uint32_t i) {
    const uint32_t ks1 = 42u;
    const uint32_t ks2 = 42u ^ 0x1BD11BDAu;
    uint32_t x1 = i + ks1;
    uint32_t x0 = x1;                       // round 1 folded (x0 was 0)
    x1 = __funnelshift_l(x1, x1, 13) ^ x0;
#define TF_R(r) { x0 += x1; x1 = __funnelshift_l(x1, x1, (r)) ^ x0; }
    TF_R(15) TF_R(26) TF_R(6)
    x0 += ks1; x1 += ks2 + 1u;
    TF_R(17) TF_R(29) TF_R(16) TF_R(24)
    x0 += ks2; x1 += 2u;
    TF_R(13) TF_R(15) TF_R(26) TF_R(6)
    x1 += ks1 + 3u;
    TF_R(17) TF_R(29) TF_R(16) TF_R(24)
    x0 += ks1; x1 += ks2 + 4u;
    TF_R(13) TF_R(15) TF_R(26) TF_R(6)
    x0 += ks2; x1 += 5u;
#undef TF_R
    return x0 ^ x1;
}

// Order-preserving float -> uint32 map (total order matching IEEE < on reals)
__device__ __forceinline__ uint32_t fmap(float v) {
    uint32_t u = __float_as_uint(v);
    return (u & 0x80000000u) ? ~u : (u | 0x80000000u);
}

__global__ void __launch_bounds__(256, 8)
fused_kernel(const float* __restrict__ logits, float* __restrict__ out) {
    __shared__ float red[256];
    __shared__ unsigned long long sbest;
    __shared__ int s_last;
    volatile __shared__ float s_thrf;    // best exactly-achieved val in this block
    volatile __shared__ float s_thrC;    // s_thrf - C0 (pre-biased screen threshold)

    int y = blockIdx.y, gx = blockIdx.x, t = threadIdx.x;

    if (y < 8) {
        // ---------------- prep block: partial softmax stats (b = y, slice gx) -----
        int b = y, px = gx;
        const float* __restrict__ row = logits + ((size_t)b * SEQ + (SEQ - 1)) * VOCAB;
        float mx = -INFINITY;
        for (int v = px * 256 + t; v < VOCAB; v += PREPP * 256) mx = fmaxf(mx, row[v]);
        red[t] = mx; __syncthreads();
        for (int s = 128; s > 0; s >>= 1) {
            if (t < s) red[t] = fmaxf(red[t], red[t + s]);
            __syncthreads();
        }
        mx = red[0];
        __syncthreads();
        float acc = 0.0f;
        for (int v = px * 256 + t; v < VOCAB; v += PREPP * 256) acc += expf(row[v] - mx);
        red[t] = acc; __syncthreads();
        for (int s = 128; s > 0; s >>= 1) {
            if (t < s) red[t] += red[t + s];
            __syncthreads();
        }
        if (t == 0) { g_pmax[b * PREPP + px] = mx; g_psum[b * PREPP + px] = red[0]; }
    } else {
        // ---------------- sampler block: lean R12 loop ----------------------------
        int r = y - 8;               // sampling row (k,l,b) flat; b = r & 7
        int b = r & 7;
        const float* __restrict__ row = logits + ((size_t)b * SEQ + (SEQ - 1)) * VOCAB;
        if (t == 0) { sbest = 0ull; s_thrf = -INFINITY; s_thrC = -INFINITY; }
        __syncthreads();

        const float tiny = 1.17549435e-38f;
        const float C0 = 6.9325f;              // > 10*ln2 + margin
        const uint32_t BITS_HI = 0xFFC00000u;  // bits >= this <=> mantissa >= 2^23-2^13
        unsigned long long best = 0ull;
        uint32_t base = (uint32_t)r * (uint32_t)VOCAB;
        int v0 = (gx << 8) + t;                // 0..1023
        uint32_t ctr = base + (uint32_t)v0;
        const float* p = row + v0;

        #define EXACT_EVAL(bitsX, lgtX, vX)                                       \
            {                                                                     \
                uint32_t mm = (bitsX) >> 9;                                       \
                float f = __uint_as_float(mm | 0x3f800000u) - 1.0f;               \
                float u = fmaxf(tiny, f + tiny);                                  \
                float val = (lgtX) - logf(-logf(u));                              \
                unsigned long long pk =                                           \
                    ((unsigned long long)fmap(val) << 32) |                       \
                    (unsigned long long)(0xFFFFFFFFu - (uint32_t)(vX));           \
                if (pk > best) best = pk;                                         \
                if (val > s_thrf) { s_thrf = val; s_thrC = val - C0; }            \
            }

        // 12 groups of 4 + 1 single = 49 strided elements, all in-range:
        // v0 + 48*1024 <= 1023 + 49152 = 50175 < VOCAB.
        #pragma unroll 1
        for (int g = 0; g < 12; ++g) {
            float thrC = s_thrC;               // one volatile LDS per group
            uint32_t b0 = tf_bits(ctr);
            uint32_t b1 = tf_bits(ctr + STRIDE);
            uint32_t b2 = tf_bits(ctr + 2 * STRIDE);
            uint32_t b3 = tf_bits(ctr + 3 * STRIDE);
            float l0 = p[0], l1 = p[STRIDE], l2 = p[2 * STRIDE], l3 = p[3 * STRIDE];
            if (b0 >= BITS_HI || l0 >= thrC) EXACT_EVAL(b0, l0, ctr - base);
            if (b1 >= BITS_HI || l1 >= thrC) EXACT_EVAL(b1, l1, ctr + STRIDE - base);
            if (b2 >= BITS_HI || l2 >= thrC) EXACT_EVAL(b2, l2, ctr + 2 * STRIDE - base);
            if (b3 >= BITS_HI || l3 >= thrC) EXACT_EVAL(b3, l3, ctr + 3 * STRIDE - base);
            ctr += 4 * STRIDE; p += 4 * STRIDE;
        }
        {   // 49th element
            float thrC = s_thrC;
            uint32_t bx = tf_bits(ctr);
            float lx = p[0];
            if (bx >= BITS_HI || lx >= thrC) EXACT_EVAL(bx, lx, ctr - base);
        }
        // remainder elements 50176..50256 (81), handled by block gx==0
        if (gx == 0 && t < 81) {
            uint32_t vr = 50176u + (uint32_t)t;
            uint32_t bx = tf_bits(base + vr);
            float lx = row[vr];
            float thrC = s_thrC;
            if (bx >= BITS_HI || lx >= thrC) EXACT_EVAL(bx, lx, vr);
        }
        #undef EXACT_EVAL

        atomicMax(&sbest, best);
        __syncthreads();
        if (t == 0) g_part[r * GX + gx] = sbest;
    }

    // ---------------- completion: last block runs the finalize --------------------
    __threadfence();
    if (t == 0) {
        unsigned int d = atomicAdd(&g_done, 1u);
        s_last = (d == TOTALB - 1);
    }
    __syncthreads();
    if (!s_last) return;
    if (t == 0) g_done = 0;          // replay-safe reset
    __threadfence();

    __shared__ float probs_s[NROWS];
    __shared__ float meanp_s[BATCH * KD];
    __shared__ float smax_s[BATCH], ssum_s[BATCH];
    int o = t;                           // output layout (b, k, l)
    int ob = o >> 5, ok = (o >> 3) & 3, ol = o & 7;
    int rowidx = ok * 64 + ol * 8 + ob;  // gumbel-field row (k, l, b)

    // softmax stats: deterministic fixed-order combine of 4 partials per batch row
    if (o < BATCH) {
        float gm = -INFINITY;
        #pragma unroll
        for (int i = 0; i < PREPP; i++) gm = fmaxf(gm, g_pmax[o * PREPP + i]);
        float s = 0.0f;
        #pragma unroll
        for (int i = 0; i < PREPP; i++)
            s += g_psum[o * PREPP + i] * expf(g_pmax[o * PREPP + i] - gm);
        smax_s[o] = gm; ssum_s[o] = s;
    }

    unsigned long long pk = g_part[rowidx * GX];
    #pragma unroll
    for (int i = 1; i < GX; i++) {
        unsigned long long q = g_part[rowidx * GX + i];
        if (q > pk) pk = q;
    }
    __syncthreads();

    uint32_t tok = 0xFFFFFFFFu - (uint32_t)(pk & 0xFFFFFFFFull);
    float lg = logits[((size_t)ob * SEQ + (SEQ - 1)) * VOCAB + tok];
    float prob = expf(lg - smax_s[ob]) / ssum_s[ob];

    out[o] = (float)tok;                               // draft_tokens
    out[NROWS + o] = prob;                             // draft_probs
    out[2 * NROWS + o] = (prob >= 0.8f) ? 1.0f : 0.0f; // accepted_mask
    probs_s[o] = prob;
    __syncthreads();

    if (o < BATCH * KD) {                              // (b, k)
        int bb = o >> 2, kk = o & 3;
        float sp = 0.0f, sm = 0.0f;
        #pragma unroll
        for (int ll = 0; ll < LD; ll++) {
            float pv = probs_s[bb * 32 + kk * 8 + ll];
            sp += pv;
            sm += (pv >= 0.8f) ? 1.0f : 0.0f;
        }
        out[3 * NROWS + o] = sm / 8.0f;                // acceptance_ratio
        meanp_s[o] = sp / 8.0f;
    }
    __syncthreads();

    if (o < BATCH) {                                   // best_draft_idx (first max)
        int bestk = 0;
        float bv = meanp_s[o * 4];
        #pragma unroll
        for (int kk = 1; kk < KD; kk++) {
            float v2 = meanp_s[o * 4 + kk];
            if (v2 > bv) { bv = v2; bestk = kk; }
        }
        out[3 * NROWS + 32 + o] = (float)bestk;
    }
}

extern "C" void kernel_launch(void* const* d_in, const int* in_sizes, int n_in,
                              void* d_out, int out_size) {
    int li = 1;
    for (int i = 0; i < n_in; i++) {
        if (in_sizes[i] == LOGITS_ELEMS) { li = i; break; }
    }
    const float* logits = (const float*)d_in[li];
    float* out = (float*)d_out;

    dim3 grid(GX, NROWS + 8);    // y 0..7: prep (hidden under sampler), 8..263: sampler
    fused_kernel<<<grid, 256>>>(logits, out);
}

// round 17
// speedup vs baseline: 1.0684x; 1.0684x over previous
#include <cuda_runtime.h>
#include <stdint.h>

#define VOCAB 50257
#define SEQ   512
#define BATCH 8
#define KD    4      // NUM_DRAFTS
#define LD    8      // DRAFT_LEN
#define NROWS 256    // KD*LD*BATCH
#define LOGITS_ELEMS (BATCH * SEQ * VOCAB)
#define GX    4      // sampler blocks per row
#define PREPP 4      // prep slices per batch row
#define NPREP (BATCH * PREPP)      // 32

// Packed per-row argmax state written per (row,gx); plain store (no reset)
__device__ unsigned long long g_part[NROWS * GX];
__device__ float g_pmax[NPREP];
__device__ float g_psum[NPREP];

// ---- JAX partitionable threefry bits for flat index i (< 2^32):
//      (o0, o1) = threefry2x32(key=(0,42), x0=0, x1=i);  bits = o0 ^ o1
__device__ __forceinline__ uint32_t tf_bits(uint32_t i) {
    const uint32_t ks1 = 42u;
    const uint32_t ks2 = 42u ^ 0x1BD11BDAu;
    uint32_t x1 = i + ks1;
    uint32_t x0 = x1;                       // round 1 folded (x0 was 0)
    x1 = __funnelshift_l(x1, x1, 13) ^ x0;
#define TF_R(r) { x0 += x1; x1 = __funnelshift_l(x1, x1, (r)) ^ x0; }
    TF_R(15) TF_R(26) TF_R(6)
    x0 += ks1; x1 += ks2 + 1u;
    TF_R(17) TF_R(29) TF_R(16) TF_R(24)
    x0 += ks2; x1 += 2u;
    TF_R(13) TF_R(15) TF_R(26) TF_R(6)
    x1 += ks1 + 3u;
    TF_R(17) TF_R(29) TF_R(16) TF_R(24)
    x0 += ks1; x1 += ks2 + 4u;
    TF_R(13) TF_R(15) TF_R(26) TF_R(6)
    x0 += ks2; x1 += 5u;
#undef TF_R
    return x0 ^ x1;
}

// Order-preserving float -> uint32 map (total order matching IEEE < on reals)
__device__ __forceinline__ uint32_t fmap(float v) {
    uint32_t u = __float_as_uint(v);
    return (u & 0x80000000u) ? ~u : (u | 0x80000000u);
}

// -------- Kernel 1: merged prep — block-local max + block-local scaled sum -----
__global__ void __launch_bounds__(256)
prep_kernel(const float* __restrict__ logits) {
    int pb = blockIdx.x;
    int b = pb >> 2, px = pb & 3, t = threadIdx.x;
    const float* __restrict__ row = logits + ((size_t)b * SEQ + (SEQ - 1)) * VOCAB;
    __shared__ float red[256];
    float mx = -INFINITY;
    for (int v = px * 256 + t; v < VOCAB; v += PREPP * 256) mx = fmaxf(mx, row[v]);
    red[t] = mx; __syncthreads();
    for (int s = 128; s > 0; s >>= 1) {
        if (t < s) red[t] = fmaxf(red[t], red[t + s]);
        __syncthreads();
    }
    mx = red[0];
    __syncthreads();
    float acc = 0.0f;
    for (int v = px * 256 + t; v < VOCAB; v += PREPP * 256) acc += expf(row[v] - mx);
    red[t] = acc; __syncthreads();
    for (int s = 128; s > 0; s >>= 1) {
        if (t < s) red[t] += red[t + s];
        __syncthreads();
    }
    if (t == 0) { g_pmax[pb] = mx; g_psum[pb] = red[0]; }
}

// -------- Kernel 2: R5 champion sampler (clz screen + shared rising threshold) -
__global__ void __launch_bounds__(256)
sample_kernel(const float* __restrict__ logits) {
    int r = blockIdx.y;          // sampling row (k,l,b) flat; b = r & 7
    int b = r & 7;
    const float* __restrict__ row = logits + ((size_t)b * SEQ + (SEQ - 1)) * VOCAB;

    __shared__ unsigned long long sbest;
    __shared__ unsigned int s_thr;       // fmap of best exact val achieved in block
    if (threadIdx.x == 0) { sbest = 0ull; s_thr = 0u; }
    __syncthreads();

    const float tiny = 1.17549435e-38f;
    const float ln2 = 0.69314718056f;
    unsigned long long best = 0ull;
    uint32_t base = (uint32_t)r * (uint32_t)VOCAB;
    for (int v = blockIdx.x * 256 + threadIdx.x; v < VOCAB; v += GX * 256) {
        uint32_t bits = tf_bits(base + (uint32_t)v);
        uint32_t m = bits >> 9;                     // 23-bit mantissa
        float lgt = __ldg(row + v);

        // Integer upper bound on gumbel: g(u) <= -ln(1-f) <= (clz(2^23-m)-8)*ln2.
        // bound >= val (real); +3e-5 covers f32 rounding of both sides.
        float cf = (float)(__clz(0x800000u - m) - 8);
        float bound = fmaf(cf, ln2, lgt) + 3e-5f;
        if (fmap(bound) >= s_thr) {                 // can't prove it loses -> exact
            float f = __uint_as_float(m | 0x3f800000u) - 1.0f;   // [0,1)
            float u = fmaxf(tiny, f + tiny);        // JAX uniform(tiny, 1)
            // exact reference formula (bit-matches XLA's __nv_logf path)
            float val = lgt - logf(-logf(u));
            unsigned long long pk =
                ((unsigned long long)fmap(val) << 32) |
                (unsigned long long)(0xFFFFFFFFu - (uint32_t)v);
            if (pk > best) best = pk;
            atomicMax(&s_thr, fmap(val));
        }
    }
    atomicMax(&sbest, best);
    __syncthreads();
    if (threadIdx.x == 0) g_part[r * GX + blockIdx.x] = sbest;
}

// -------- Kernel 3: epilogue — rescale-combine partials + write 808 floats -----
__global__ void __launch_bounds__(NROWS)
finalize_kernel(const float* __restrict__ logits, float* __restrict__ out) {
    __shared__ float probs_s[NROWS];
    __shared__ float meanp_s[BATCH * KD];
    __shared__ float smax_s[BATCH], ssum_s[BATCH];
    int o = threadIdx.x;                 // output layout (b, k, l)
    int b = o >> 5, k = (o >> 3) & 3, l = o & 7;
    int rowidx = k * 64 + l * 8 + b;     // gumbel-field row (k, l, b)

    if (o < BATCH) {                     // deterministic fixed-order combine
        float gm = -INFINITY;
        #pragma unroll
        for (int i = 0; i < PREPP; i++) gm = fmaxf(gm, g_pmax[o * PREPP + i]);
        float s = 0.0f;
        #pragma unroll
        for (int i = 0; i < PREPP; i++)
            s += g_psum[o * PREPP + i] * expf(g_pmax[o * PREPP + i] - gm);
        smax_s[o] = gm; ssum_s[o] = s;
    }

    unsigned long long pk = g_part[rowidx * GX];
    #pragma unroll
    for (int i = 1; i < GX; i++) {
        unsigned long long q = g_part[rowidx * GX + i];
        if (q > pk) pk = q;
    }
    __syncthreads();

    uint32_t tok = 0xFFFFFFFFu - (uint32_t)(pk & 0xFFFFFFFFull);
    float lg = logits[((size_t)b * SEQ + (SEQ - 1)) * VOCAB + tok];
    float prob = expf(lg - smax_s[b]) / ssum_s[b];

    out[o] = (float)tok;                               // draft_tokens
    out[NROWS + o] = prob;                             // draft_probs
    out[2 * NROWS + o] = (prob >= 0.8f) ? 1.0f : 0.0f; // accepted_mask
    probs_s[o] = prob;
    __syncthreads();

    if (o < BATCH * KD) {                              // (b, k)
        int bb = o >> 2, kk = o & 3;
        float sp = 0.0f, sm = 0.0f;
        #pragma unroll
        for (int ll = 0; ll < LD; ll++) {
            float pv = probs_s[bb * 32 + kk * 8 + ll];
            sp += pv;
            sm += (pv >= 0.8f) ? 1.0f : 0.0f;
        }
        out[3 * NROWS + o] = sm / 8.0f;                // acceptance_ratio
        meanp_s[o] = sp / 8.0f;
    }
    __syncthreads();

    if (o < BATCH) {                                   // best_draft_idx (first max)
        int bestk = 0;
        float bv = meanp_s[o * 4];
        #pragma unroll
        for (int kk = 1; kk < KD; kk++) {
            float v2 = meanp_s[o * 4 + kk];
            if (v2 > bv) { bv = v2; bestk = kk; }
        }
        out[3 * NROWS + 32 + o] = (float)bestk;
    }
}

extern "C" void kernel_launch(void* const* d_in, const int* in_sizes, int n_in,
                              void* d_out, int out_size) {
    int li = 1;
    for (int i = 0; i < n_in; i++) {
        if (in_sizes[i] == LOGITS_ELEMS) { li = i; break; }
    }
    const float* logits = (const float*)d_in[li];
    float* out = (float*)d_out;

    prep_kernel<<<NPREP, 256>>>(logits);
    dim3 gridB(GX, NROWS);
    sample_kernel<<<gridB, 256>>>(logits);
    finalize_kernel<<<1, NROWS>>>(logits, out);
}